// round 7
// baseline (speedup 1.0000x reference)
#include <cuda_runtime.h>
#include <math.h>

#define GRID 128
#define TPB  512
#define Bp   512
#define Dd   64
#define Cc   512
#define NBs  8
#define MC   8
#define NBINS 32768
#define BIN_SC ((float)NBINS/64.0f)

__device__ float g_hA[Bp*Cc];
__device__ float g_hB[Bp*Cc];
__device__ float g_d2[Bp*Bp];
__device__ float g_temb[NBs*2*Cc];
__device__ float g_tg1[NBs*Cc];
__device__ float g_bias1[NBs*Cc];
__device__ float g_betas[NBs+1];
__device__ int   g_hist[2][NBINS];
__device__ unsigned long long g_bar = 0ULL;
// weights pre-converted to tf32 bit patterns (stored as float bits)
__device__ float g_Win[Dd*Cc];
__device__ float g_Wh[3*Cc*Cc];
__device__ float g_Wout[Cc*Dd];

#define ASTR 36   // A smem row stride (floats): conflict-free frag loads
#define WSTR 40   // W smem row stride

struct SmG { float A[4][2][64*ASTR]; float W[4][2][32*WSTR]; float red[3][64*33]; };
struct SmP { float Xi[32*64]; float Xj[64*64]; };
struct SmU { float w[4][Bp]; float2 rp[4][2][64]; float compm[4][MC]; float wm[4][MC]; };
struct SmM { int cnt[TPB]; float v[2]; };
union Smem { SmG g; SmP p; SmU u; SmM m; };

__device__ __forceinline__ float gelu_t(float x){
    float x3 = x*x*x;
    return 0.5f*x*(1.0f+tanhf(0.7978845608028654f*(x+0.044715f*x3)));
}

__device__ __forceinline__ unsigned f2tf(float x){
    unsigned u;
    asm("cvt.rna.tf32.f32 %0, %1;" : "=r"(u) : "f"(x));
    return u;
}
__device__ __forceinline__ float f2tf_f(float x){ return __uint_as_float(f2tf(x)); }

__device__ __forceinline__ void mma_tf32(float* acc,
    unsigned a0, unsigned a1, unsigned a2, unsigned a3,
    unsigned b0, unsigned b1)
{
    asm volatile(
        "mma.sync.aligned.m16n8k8.row.col.f32.tf32.tf32.f32 "
        "{%0,%1,%2,%3}, {%4,%5,%6,%7}, {%8,%9}, {%0,%1,%2,%3};"
        : "+f"(acc[0]), "+f"(acc[1]), "+f"(acc[2]), "+f"(acc[3])
        : "r"(a0), "r"(a1), "r"(a2), "r"(a3), "r"(b0), "r"(b1));
}

// software grid barrier (monotone counter; safe across graph replays)
__device__ __forceinline__ void gridbar(){
    __threadfence();
    __syncthreads();
    if (threadIdx.x == 0){
        unsigned long long old = atomicAdd(&g_bar, 1ULL);
        unsigned long long target = (old/GRID + 1ULL)*GRID;
        while (*(volatile unsigned long long*)&g_bar < target) { }
    }
    __syncthreads();
    __threadfence();
}

// one 64x32 output tile of C = act(A@W + bias) via tf32 tensor cores.
// 512 threads: 4 warp-groups split K (nsplit = min(4, klen/32)); smem
// reduction, group 0 does the epilogue. W holds tf32 bit patterns.
// convA: convert A to tf32 while staging. convOut: store tf32-rounded output.
__device__ __forceinline__ void gemm_tile_tc(
    const float* __restrict__ A, int Astr, const float* __restrict__ W, int Wstr,
    int m0, int n0, int klen,
    const float* __restrict__ bias, int act, int convA, int convOut,
    float* __restrict__ C, int Cstr, Smem* sm)
{
    int tid  = threadIdx.x;
    int gid  = tid >> 7;            // K-split group 0..3
    int tg   = tid & 127;
    int warp = tg >> 5, lane = tid & 31;
    int g = lane >> 2, t = lane & 3;

    int nsplit = (klen >= 128) ? 4 : (klen >> 5);
    int kpart  = klen / nsplit;
    int NC     = kpart >> 5;
    bool active = gid < nsplit;
    int kb0 = gid * kpart;

    int arow = tg >> 1;             // 0..63
    int kseg = (tg & 1) * 16;       // 0/16
    int wk   = tg >> 2;             // 0..31
    int nseg = (tg & 3) * 8;        // 0,8,16,24

    float acc[4][4] = {};
    float4 ra[4], rw[2];

    if (active){
        #pragma unroll
        for (int q = 0; q < 4; q++)
            ra[q] = *(const float4*)&A[(size_t)(m0+arow)*Astr + kb0 + kseg + 4*q];
        #pragma unroll
        for (int q = 0; q < 2; q++)
            rw[q] = *(const float4*)&W[(size_t)(kb0+wk)*Wstr + n0 + nseg + 4*q];
        if (convA){
            #pragma unroll
            for (int q = 0; q < 4; q++){
                ra[q].x = f2tf_f(ra[q].x); ra[q].y = f2tf_f(ra[q].y);
                ra[q].z = f2tf_f(ra[q].z); ra[q].w = f2tf_f(ra[q].w);
            }
        }
        float* As = sm->g.A[gid][0]; float* Ws = sm->g.W[gid][0];
        #pragma unroll
        for (int q = 0; q < 4; q++) *(float4*)&As[arow*ASTR + kseg + 4*q] = ra[q];
        #pragma unroll
        for (int q = 0; q < 2; q++) *(float4*)&Ws[wk*WSTR + nseg + 4*q] = rw[q];
    }

    for (int c = 0; c < NC; c++){
        __syncthreads();
        int cb = c & 1;
        if (active && c+1 < NC){
            int kb = kb0 + (c+1)*32;
            #pragma unroll
            for (int q = 0; q < 4; q++)
                ra[q] = *(const float4*)&A[(size_t)(m0+arow)*Astr + kb + kseg + 4*q];
            #pragma unroll
            for (int q = 0; q < 2; q++)
                rw[q] = *(const float4*)&W[(size_t)(kb+wk)*Wstr + n0 + nseg + 4*q];
            if (convA){
                #pragma unroll
                for (int q = 0; q < 4; q++){
                    ra[q].x = f2tf_f(ra[q].x); ra[q].y = f2tf_f(ra[q].y);
                    ra[q].z = f2tf_f(ra[q].z); ra[q].w = f2tf_f(ra[q].w);
                }
            }
        }
        if (active){
            const float* As = sm->g.A[gid][cb];
            const float* Ws = sm->g.W[gid][cb];
            #pragma unroll
            for (int kk = 0; kk < 4; kk++){
                int ab = (16*warp + g)*ASTR + kk*8;
                unsigned a0 = __float_as_uint(As[ab + t]);
                unsigned a1 = __float_as_uint(As[ab + 8*ASTR + t]);
                unsigned a2 = __float_as_uint(As[ab + t + 4]);
                unsigned a3 = __float_as_uint(As[ab + 8*ASTR + t + 4]);
                #pragma unroll
                for (int c4 = 0; c4 < 4; c4++){
                    unsigned b0 = __float_as_uint(Ws[(kk*8 + t)*WSTR + c4*8 + g]);
                    unsigned b1 = __float_as_uint(Ws[(kk*8 + t + 4)*WSTR + c4*8 + g]);
                    mma_tf32(acc[c4], a0, a1, a2, a3, b0, b1);
                }
            }
            if (c+1 < NC){
                int nb = cb ^ 1;
                float* As2 = sm->g.A[gid][nb]; float* Ws2 = sm->g.W[gid][nb];
                #pragma unroll
                for (int q = 0; q < 4; q++) *(float4*)&As2[arow*ASTR + kseg + 4*q] = ra[q];
                #pragma unroll
                for (int q = 0; q < 2; q++) *(float4*)&Ws2[wk*WSTR + nseg + 4*q] = rw[q];
            }
        }
    }

    __syncthreads();
    int r0 = 16*warp + g;
    if (active && gid > 0){
        float* red = sm->g.red[gid-1];
        #pragma unroll
        for (int c4 = 0; c4 < 4; c4++){
            int col = c4*8 + 2*t;
            red[r0*33 + col]       = acc[c4][0];
            red[r0*33 + col + 1]   = acc[c4][1];
            red[(r0+8)*33 + col]   = acc[c4][2];
            red[(r0+8)*33 + col+1] = acc[c4][3];
        }
    }
    __syncthreads();
    if (gid == 0){
        #pragma unroll
        for (int c4 = 0; c4 < 4; c4++){
            int col = c4*8 + 2*t;
            float v00 = acc[c4][0], v01 = acc[c4][1];
            float v10 = acc[c4][2], v11 = acc[c4][3];
            for (int q = 0; q < nsplit-1; q++){
                const float* red = sm->g.red[q];
                v00 += red[r0*33 + col];
                v01 += red[r0*33 + col + 1];
                v10 += red[(r0+8)*33 + col];
                v11 += red[(r0+8)*33 + col+1];
            }
            int n = n0 + col;
            if (bias){ v00 += bias[n]; v01 += bias[n+1]; v10 += bias[n]; v11 += bias[n+1]; }
            if (act){ v00 = gelu_t(v00); v01 = gelu_t(v01); v10 = gelu_t(v10); v11 = gelu_t(v11); }
            if (convOut){ v00 = f2tf_f(v00); v01 = f2tf_f(v01); v10 = f2tf_f(v10); v11 = f2tf_f(v11); }
            C[(size_t)(m0+r0)*Cstr + n]       = v00;
            C[(size_t)(m0+r0)*Cstr + n + 1]   = v01;
            C[(size_t)(m0+r0+8)*Cstr + n]     = v10;
            C[(size_t)(m0+r0+8)*Cstr + n + 1] = v11;
        }
    }
    __syncthreads();
}

// 32x64 tile of pairwise squared distances + histogram (512 threads)
__device__ __forceinline__ void pairwise_tile(const float* __restrict__ x, int i0, int j0,
                                              int* __restrict__ hist, Smem* sm){
    int tid = threadIdx.x;
    {   // Xi: 32 rows x 64 k, transposed
        int r = tid>>4, c4 = (tid&15)*4;
        if (r < 32){
            float4 v = *(const float4*)&x[(i0+r)*Dd + c4];
            sm->p.Xi[(c4+0)*32+r]=v.x; sm->p.Xi[(c4+1)*32+r]=v.y;
            sm->p.Xi[(c4+2)*32+r]=v.z; sm->p.Xi[(c4+3)*32+r]=v.w;
        }
    }
    #pragma unroll
    for (int q = 0; q < 2; q++){
        int idx = tid + 512*q;
        int row = idx>>4, c4 = (idx&15)*4;
        float4 v = *(const float4*)&x[(j0+row)*Dd + c4];
        sm->p.Xj[(c4+0)*64+row]=v.x; sm->p.Xj[(c4+1)*64+row]=v.y;
        sm->p.Xj[(c4+2)*64+row]=v.z; sm->p.Xj[(c4+3)*64+row]=v.w;
    }
    __syncthreads();
    int ty = tid>>5, tx = tid&31;          // 16x32 thread grid, 2x2 micro
    float acc[2][2] = {};
    #pragma unroll
    for (int k = 0; k < 64; k++){
        float2 a = *(const float2*)&sm->p.Xi[k*32 + ty*2];
        float2 b = *(const float2*)&sm->p.Xj[k*64 + tx*2];
        float d;
        d=a.x-b.x; acc[0][0]+=d*d;  d=a.x-b.y; acc[0][1]+=d*d;
        d=a.y-b.x; acc[1][0]+=d*d;  d=a.y-b.y; acc[1][1]+=d*d;
    }
    #pragma unroll
    for (int i = 0; i < 2; i++){
        int gi = i0 + ty*2 + i;
        #pragma unroll
        for (int j = 0; j < 2; j++){
            int gj = j0 + tx*2 + j;
            float d2 = acc[i][j];
            g_d2[gi*Bp + gj] = d2;
            float dist = sqrtf(d2 > 0.f ? d2 : 1e-12f);
            int bin = (int)(dist*BIN_SC);
            if (bin > NBINS-1) bin = NBINS-1;
            atomicAdd(&hist[bin], 1);
        }
    }
    __syncthreads();
}

// every block computes the exact median locally (prefix scan over chunk counts)
__device__ __forceinline__ float median_local(const int* __restrict__ hist, Smem* sm){
    int tid = threadIdx.x;
    const int per = NBINS/TPB;   // 64
    int ssum = 0;
    #pragma unroll 8
    for (int b = 0; b < per; b++) ssum += hist[tid*per + b];
    sm->m.cnt[tid] = ssum;
    __syncthreads();
    #pragma unroll
    for (int off = 1; off < TPB; off <<= 1){
        int v = (tid >= off) ? sm->m.cnt[tid-off] : 0;
        __syncthreads();
        sm->m.cnt[tid] += v;
        __syncthreads();
    }
    long long k1 = (long long)Bp*Bp/2, k2 = k1 + 1;
    int prev = tid ? sm->m.cnt[tid-1] : 0;
    int cur  = sm->m.cnt[tid];
    if (prev < k1 && k1 <= cur){
        int cum = prev, b = tid*per;
        while (cum + hist[b] < k1){ cum += hist[b]; b++; }
        sm->m.v[0] = ((float)b + 0.5f)/BIN_SC;
    }
    if (prev < k2 && k2 <= cur){
        int cum = prev, b = tid*per;
        while (cum + hist[b] < k2){ cum += hist[b]; b++; }
        sm->m.v[1] = ((float)b + 0.5f)/BIN_SC;
    }
    __syncthreads();
    float med = 0.5f*(sm->m.v[0] + sm->m.v[1]);
    float ht = med*med / logf((float)Bp);
    __syncthreads();     // everyone has read v[] before the union is reused
    return ht;
}

__global__ void __launch_bounds__(TPB, 1)
cmcd_fused(const float* __restrict__ particles, const float* __restrict__ noises,
           const float* __restrict__ grid_t, const float* __restrict__ eps,
           const float* __restrict__ means, const float* __restrict__ phase,
           const float* __restrict__ in_W, const float* __restrict__ in_b,
           const float* __restrict__ t_W1, const float* __restrict__ t_b1,
           const float* __restrict__ t_W2, const float* __restrict__ t_b2,
           const float* __restrict__ h_W, const float* __restrict__ h_b,
           const float* __restrict__ out_W, const float* __restrict__ out_b,
           float* __restrict__ out)
{
    extern __shared__ unsigned char smem_raw[];
    Smem* sm = reinterpret_cast<Smem*>(smem_raw);
    int blk = blockIdx.x, tid = threadIdx.x;
    int gtid = blk*TPB + tid;
    const int NT = GRID*TPB;

    // ── S0: copy slice 0, zero hists, temb, betas, convert weights to tf32 ──
    for (int idx = gtid; idx < Bp*Dd; idx += NT) out[idx] = particles[idx];
    for (int idx = gtid; idx < 2*NBINS; idx += NT) g_hist[0][idx] = 0;
    for (int idx = gtid; idx < Dd*Cc; idx += NT) g_Win[idx] = f2tf_f(in_W[idx]);
    for (int idx = gtid; idx < 3*Cc*Cc; idx += NT) g_Wh[idx] = f2tf_f(h_W[idx]);
    for (int idx = gtid; idx < Cc*Dd; idx += NT) g_Wout[idx] = f2tf_f(out_W[idx]);
    if (gtid < NBs*2*Cc){
        int idx = gtid;
        int s = idx >> 10, c = idx & 1023;
        float t = (float)s;
        int cc = (c < Cc) ? c : c - Cc;
        float coeff = 0.1f + (float)cc*(99.9f/511.0f);
        float e = coeff*t + phase[cc];
        g_temb[idx] = (c < Cc) ? sinf(e) : cosf(e);
    }
    if (gtid == 0){
        float cum = 0.f;
        g_betas[0] = 0.f;
        for (int j = 0; j < NBs; j++){
            float sg = 1.f/(1.f+expf(-grid_t[j]));
            cum += sg;
            g_betas[j+1] = cum;
        }
        float inv = 1.f/cum;
        for (int j = 1; j <= NBs; j++) g_betas[j] *= inv;
    }
    gridbar();

    // ── S1: t-MLP layer 1 (8-way K-split + shuffle reduce) ──
    if (gtid < 8*NBs*Cc){
        int oidx = gtid >> 3;       // 0..4095
        int sl   = gtid & 7;
        int s = oidx >> 9, c = oidx & 511;
        float acc = 0.f;
        const float* tb = g_temb + s*2*Cc;
        int kb = sl*128;
        #pragma unroll 4
        for (int k = kb; k < kb+128; k++) acc += tb[k]*t_W1[k*Cc + c];
        #pragma unroll
        for (int o = 1; o < 8; o <<= 1) acc += __shfl_xor_sync(0xffffffffu, acc, o);
        if (sl == 0) g_tg1[oidx] = gelu_t(acc + t_b1[c]);
    }
    gridbar();

    // ── S2: t-MLP layer 2 + in_b → fused input bias ──
    if (gtid < 8*NBs*Cc){
        int oidx = gtid >> 3;
        int sl   = gtid & 7;
        int s = oidx >> 9, c = oidx & 511;
        float acc = 0.f;
        const float* gb = g_tg1 + s*Cc;
        int kb = sl*64;
        #pragma unroll 4
        for (int k = kb; k < kb+64; k++) acc += gb[k]*t_W2[k*Cc + c];
        #pragma unroll
        for (int o = 1; o < 8; o <<= 1) acc += __shfl_xor_sync(0xffffffffu, acc, o);
        if (sl == 0) g_bias1[oidx] = acc + t_b2[c] + in_b[c];
    }
    gridbar();

    int m0 = (blk >> 4) * 64;     // 8 m-tiles of 64 rows
    int n0 = (blk & 15) * 32;     // 16 n-tiles of 32 cols

    for (int s = 0; s < NBs; s++){
        const float* x = out + (size_t)s*Bp*Dd;
        float* xn      = out + (size_t)(s+1)*Bp*Dd;
        int par = s & 1;

        // ── P1: input layer (K=64, conv A) + pairwise d2/hist ──
        gemm_tile_tc(x, Dd, g_Win, Cc, m0, n0, Dd, g_bias1 + s*Cc, 1, 1, 1, g_hA, Cc, sm);
        pairwise_tile(x, (blk>>3)*32, (blk&7)*64, g_hist[par], sm);
        gridbar();

        // ── P2-P4: hidden layers ──
        gemm_tile_tc(g_hA, Cc, g_Wh + 0*Cc*Cc, Cc, m0, n0, Cc, h_b + 0*Cc, 1, 0, 1, g_hB, Cc, sm);
        gridbar();
        gemm_tile_tc(g_hB, Cc, g_Wh + 1*Cc*Cc, Cc, m0, n0, Cc, h_b + 1*Cc, 1, 0, 1, g_hA, Cc, sm);
        gridbar();
        gemm_tile_tc(g_hA, Cc, g_Wh + 2*Cc*Cc, Cc, m0, n0, Cc, h_b + 2*Cc, 1, 0, 1, g_hB, Cc, sm);
        gridbar();

        // ── P6: median + out-layer GEMV (block-local rows) + update ──
        {
            float ht = median_local(g_hist[par], sm);
            float inv_ht = 1.f/ht;
            int p   = tid >> 7;          // particle slot 0..3
            int sub = (tid >> 6) & 1;    // j/k half
            int d   = tid & 63;
            int i   = blk*4 + p;
            float dt = eps[0];
            float t = g_betas[s];
            float s2dt = sqrtf(2.f*dt);
            float xi_d = x[i*Dd + d];

            // RBF weights for this particle's half
            #pragma unroll
            for (int q = 0; q < 4; q++){
                int j = sub*256 + q*64 + d;
                sm->u.w[p][j] = expf(-g_d2[i*Bp + j]*inv_ht);
            }
            // mixture component logits
            if (sub == 0 && d < MC){
                float sacc = 0.f;
                #pragma unroll 4
                for (int k = 0; k < Dd; k++){
                    float df = x[i*Dd + k] - means[d*Dd + k];
                    sacc += df*df;
                }
                sm->u.compm[p][d] = -0.5f*sacc;
            }
            __syncthreads();
            if (sub == 0 && d == 0){
                float mx = sm->u.compm[p][0];
                for (int m = 1; m < MC; m++) mx = fmaxf(mx, sm->u.compm[p][m]);
                float se = 0.f;
                for (int m = 0; m < MC; m++){
                    float e = expf(sm->u.compm[p][m]-mx);
                    sm->u.wm[p][m] = e; se += e;
                }
                float inv = 1.f/se;
                for (int m = 0; m < MC; m++) sm->u.wm[p][m] *= inv;
            }
            __syncthreads();

            // repulsion partial over this thread's j-half
            float r = 0.f;
            const float* wrow = sm->u.w[p];
            {
                int jb = sub*256;
                #pragma unroll 8
                for (int j = jb; j < jb+256; j++)
                    r += wrow[j]*(xi_d - x[j*Dd + d]);
            }
            // score GEMV partial over this thread's k-half
            float sc = 0.f;
            {
                const float* hb = g_hB + (size_t)i*Cc;
                int kb = sub*256;
                #pragma unroll 8
                for (int k = kb; k < kb+256; k++)
                    sc += hb[k]*out_W[k*Dd + d];
            }
            if (sub == 1){
                sm->u.rp[p][1][d] = make_float2(r, sc);
            }
            __syncthreads();
            if (sub == 0){
                float2 o2 = sm->u.rp[p][1][d];
                r  += o2.x;
                sc += o2.y + out_b[d];
                float wbar = 0.f;
                #pragma unroll
                for (int m = 0; m < MC; m++) wbar += sm->u.wm[p][m]*means[m*Dd + d];
                float drift = t*wbar - xi_d - sc;
                float nv = noises[((size_t)s*Bp + i)*Dd + d];
                xn[i*Dd + d] = xi_d + dt*drift + s2dt*nv + 0.1f*dt*inv_ht*r;
            }
            // zero the OTHER histogram (used next step)
            for (int idx = gtid; idx < NBINS; idx += NT) g_hist[par^1][idx] = 0;
        }
        gridbar();
    }
}

extern "C" void kernel_launch(void* const* d_in, const int* in_sizes, int n_in,
                              void* d_out, int out_size){
    const float* particles = (const float*)d_in[0];
    const float* noises    = (const float*)d_in[1];
    const float* grid_t    = (const float*)d_in[2];
    const float* eps       = (const float*)d_in[3];
    const float* means     = (const float*)d_in[4];
    const float* phase     = (const float*)d_in[5];
    const float* in_W      = (const float*)d_in[6];
    const float* in_b      = (const float*)d_in[7];
    const float* t_W1      = (const float*)d_in[8];
    const float* t_b1      = (const float*)d_in[9];
    const float* t_W2      = (const float*)d_in[10];
    const float* t_b2      = (const float*)d_in[11];
    const float* h_W       = (const float*)d_in[12];
    const float* h_b       = (const float*)d_in[13];
    const float* out_W     = (const float*)d_in[14];
    const float* out_b     = (const float*)d_in[15];
    float* out = (float*)d_out;

    static int smem_set = -1;
    int smem_bytes = (int)sizeof(Smem);
    if (smem_set < 0){
        cudaFuncSetAttribute(cmcd_fused, cudaFuncAttributeMaxDynamicSharedMemorySize, smem_bytes);
        smem_set = 1;
    }

    cmcd_fused<<<GRID, TPB, smem_bytes>>>(particles, noises, grid_t, eps, means, phase,
                                          in_W, in_b, t_W1, t_b1, t_W2, t_b2,
                                          h_W, h_b, out_W, out_b, out);
}